// round 9
// baseline (speedup 1.0000x reference)
#include <cuda_runtime.h>
#include <stdint.h>

// ParallelTransport: out[e, c, :] = R(rho[e]) @ x[row[e], c, :]
// x: (1, N, 32, 2) fp32 ; edge_index: (2, E) int32 ; rho: (E,) fp32
// out: (1, E, 32, 2) fp32
//
// R8: each 16-thread group handles 4 consecutive edges.
//  - 1 int4 index load + 1 float4 rho load per thread (group-broadcast)
//    instead of 4+4 scalar loads -> fewer L1 wavefronts (R3 showed L1tex 67%
//    as the hottest stage).
//  - 4 independent float4 gathers per thread (MLP=4, same as best config).
//  - streaming stores protect the L2-resident 12.8 MB x table.
// Block = 256 thr = 16 groups = 64 edges. Check-free main grid; tail kernel
// covers E % 64 edges (zero for E = 1.6M).

#define TPB 256

__global__ void __launch_bounds__(TPB)
pt_kernel(const float4* __restrict__ x4,
          const int4* __restrict__ row4,
          const float4* __restrict__ rho4,
          float4* __restrict__ out)
{
    unsigned tid = threadIdx.x;
    unsigned g   = tid >> 4;          // group within block (0..15)
    unsigned sub = tid & 15u;         // float4 slot within edge row (0..15)
    unsigned grp = blockIdx.x * 16u + g;   // global group = edge/4

    int4   idx = __ldg(&row4[grp]);   // 4 edge row indices (broadcast in group)
    float4 rv  = __ldg(&rho4[grp]);   // 4 rho values

    // 4 independent gathers in flight
    float4 v0 = __ldg(&x4[(unsigned)idx.x * 16u + sub]);
    float4 v1 = __ldg(&x4[(unsigned)idx.y * 16u + sub]);
    float4 v2 = __ldg(&x4[(unsigned)idx.z * 16u + sub]);
    float4 v3 = __ldg(&x4[(unsigned)idx.w * 16u + sub]);

    unsigned obase = grp * 64u + sub;      // (grp*4 edges) * 16 slots

    float s, c;
    float4 o;

    __sincosf(rv.x, &s, &c);
    o.x = fmaf(c, v0.x, -s * v0.y);  o.y = fmaf(s, v0.x, c * v0.y);
    o.z = fmaf(c, v0.z, -s * v0.w);  o.w = fmaf(s, v0.z, c * v0.w);
    __stcs(&out[obase], o);

    __sincosf(rv.y, &s, &c);
    o.x = fmaf(c, v1.x, -s * v1.y);  o.y = fmaf(s, v1.x, c * v1.y);
    o.z = fmaf(c, v1.z, -s * v1.w);  o.w = fmaf(s, v1.z, c * v1.w);
    __stcs(&out[obase + 16u], o);

    __sincosf(rv.z, &s, &c);
    o.x = fmaf(c, v2.x, -s * v2.y);  o.y = fmaf(s, v2.x, c * v2.y);
    o.z = fmaf(c, v2.z, -s * v2.w);  o.w = fmaf(s, v2.z, c * v2.w);
    __stcs(&out[obase + 32u], o);

    __sincosf(rv.w, &s, &c);
    o.x = fmaf(c, v3.x, -s * v3.y);  o.y = fmaf(s, v3.x, c * v3.y);
    o.z = fmaf(c, v3.z, -s * v3.w);  o.w = fmaf(s, v3.z, c * v3.w);
    __stcs(&out[obase + 48u], o);
}

// Tail: per-slot fallback for edges not covered by full blocks (E % 64)
__global__ void __launch_bounds__(TPB)
pt_tail_kernel(const float* __restrict__ x,
               const int* __restrict__ row,
               const float* __restrict__ rho,
               float4* __restrict__ out,
               unsigned start, unsigned total)
{
    unsigned slot = start + blockIdx.x * TPB + threadIdx.x;
    if (slot >= total) return;
    unsigned e = slot >> 4, sub = slot & 15u;
    int   r  = __ldg(&row[e]);
    float rv = __ldg(&rho[e]);
    float s, c;
    __sincosf(rv, &s, &c);
    float4 v = __ldg(reinterpret_cast<const float4*>(x) + ((unsigned)r * 16u + sub));
    float4 o;
    o.x = fmaf(c, v.x, -s * v.y);
    o.y = fmaf(s, v.x,  c * v.y);
    o.z = fmaf(c, v.z, -s * v.w);
    o.w = fmaf(s, v.z,  c * v.w);
    __stcs(&out[slot], o);
}

extern "C" void kernel_launch(void* const* d_in, const int* in_sizes, int n_in,
                              void* d_out, int out_size)
{
    const float* x    = (const float*)d_in[0];
    const int*   eidx = (const int*)d_in[1];   // (2, E): first E entries = row
    const float* rho  = (const float*)d_in[2];

    unsigned E = (unsigned)in_sizes[2];
    unsigned full_blocks = E / 64u;            // 64 edges per block
    unsigned covered_edges = full_blocks * 64u;

    if (full_blocks)
        pt_kernel<<<full_blocks, TPB>>>(
            (const float4*)x, (const int4*)eidx, (const float4*)rho,
            (float4*)d_out);

    if (covered_edges < E) {
        unsigned start = covered_edges * 16u;
        unsigned total = E * 16u;
        unsigned rem   = total - start;
        unsigned tb    = (rem + TPB - 1) / TPB;
        pt_tail_kernel<<<tb, TPB>>>(x, eidx, rho, (float4*)d_out, start, total);
    }
}

// round 10
// speedup vs baseline: 1.5463x; 1.5463x over previous
#include <cuda_runtime.h>
#include <stdint.h>

// ParallelTransport: out[e, c, :] = R(rho[e]) @ x[row[e], c, :]
// x: (1, N, 32, 2) fp32 ; edge_index: (2, E) int32 ; rho: (E,) fp32
// out: (1, E, 32, 2) fp32
//
// R10 = R3 (best: 64.0 us) + 32-bit slot arithmetic.
// 16 threads per edge, one float4 (2 channels) per thread, ITER=4 slots
// per thread in batched phases: all index/rho loads, then 4 independent
// gathers (MLP=4 on the L2-resident 12.8 MB x table), then rotate +
// streaming stores (keep x resident in L2).

#define ITER 4
#define TPB  256

__global__ void __launch_bounds__(TPB)
pt_kernel(const float* __restrict__ x,
          const int* __restrict__ row,
          const float* __restrict__ rho,
          float4* __restrict__ out,
          unsigned total /* E * 16 float4 slots, < 2^31 */)
{
    unsigned base = blockIdx.x * (TPB * ITER) + threadIdx.x;

    bool   ok[ITER];
    int    r[ITER];
    float  rv[ITER];
    float4 v[ITER];

    // Phase 1: index + rho loads (L1-broadcast within 16-lane groups)
    #pragma unroll
    for (int i = 0; i < ITER; i++) {
        unsigned slot = base + i * TPB;
        unsigned e = slot >> 4;
        ok[i] = slot < total;
        r[i]  = ok[i] ? __ldg(&row[e]) : 0;
        rv[i] = ok[i] ? __ldg(&rho[e]) : 0.0f;
    }

    // Phase 2: dependent gathers — 4 independent chains in flight
    #pragma unroll
    for (int i = 0; i < ITER; i++) {
        unsigned sub = (base + i * TPB) & 15u;
        v[i] = __ldg(reinterpret_cast<const float4*>(x)
                     + ((unsigned)r[i] * 16u + sub));
    }

    // Phase 3: rotate + streaming store
    #pragma unroll
    for (int i = 0; i < ITER; i++) {
        if (!ok[i]) continue;
        float s, c;
        __sincosf(rv[i], &s, &c);
        float4 o;
        o.x = fmaf(c, v[i].x, -s * v[i].y);
        o.y = fmaf(s, v[i].x,  c * v[i].y);
        o.z = fmaf(c, v[i].z, -s * v[i].w);
        o.w = fmaf(s, v[i].z,  c * v[i].w);
        __stcs(&out[base + i * TPB], o);
    }
}

extern "C" void kernel_launch(void* const* d_in, const int* in_sizes, int n_in,
                              void* d_out, int out_size)
{
    const float* x    = (const float*)d_in[0];
    const int*   eidx = (const int*)d_in[1];   // (2, E): first E entries = row
    const float* rho  = (const float*)d_in[2];

    unsigned E = (unsigned)in_sizes[2];
    unsigned total = E * 16u;                  // float4 slots

    unsigned per_block = TPB * ITER;
    unsigned blocks = (total + per_block - 1) / per_block;

    pt_kernel<<<blocks, TPB>>>(x, eidx, rho, (float4*)d_out, total);
}